// round 5
// baseline (speedup 1.0000x reference)
#include <cuda_runtime.h>
#include <cstdint>
#include <cstddef>

// ---------------- problem constants ----------------
#define NB 4
#define NT 2048
#define NM 1024
#define NH 2048
#define NE 8
#define NS (NB * NT)       // 8192 tokens
#define NC 2048            // expert capacity

// ---------------- device scratch (no allocs allowed) ----------------
__device__ int   g_topi[NS * 2];
__device__ float g_gate[NS * 2];
__device__ int   g_tok[NE * NC];
__device__ float g_gts[NE * NC];
__device__ int   g_ne[NE];
__device__ __align__(16) float g_w2s[NE * NH];
__device__ float g_b2s[NE];
__device__ float g_osum[NS];

// ---------------- f32x2 helpers (sm_103a FFMA2) ----------------
__device__ __forceinline__ unsigned long long pack2(float a, float b) {
    unsigned long long r;
    asm("mov.b64 %0, {%1, %2};" : "=l"(r)
        : "r"(__float_as_uint(a)), "r"(__float_as_uint(b)));
    return r;
}
__device__ __forceinline__ void fma2(unsigned long long& c, unsigned long long a,
                                     unsigned long long b) {
    asm("fma.rn.f32x2 %0, %1, %2, %0;" : "+l"(c) : "l"(a), "l"(b));
}
__device__ __forceinline__ float2 unpack2(unsigned long long v) {
    unsigned lo, hi;
    asm("mov.b64 {%0, %1}, %2;" : "=r"(lo), "=r"(hi) : "l"(v));
    return make_float2(__uint_as_float(lo), __uint_as_float(hi));
}

// ---------------- w2 column-sum: w2sum[e,h] = sum_m w2[e,h,m] ----------------
// grid: (NE*NH/8) blocks x 256 threads, one warp per (e,h) row.
__global__ void w2sum_kernel(const float* __restrict__ w2) {
    int r = blockIdx.x * 8 + (threadIdx.x >> 5);
    int lane = threadIdx.x & 31;
    const float* p = w2 + (size_t)r * NM;
    float s = 0.f;
    #pragma unroll 4
    for (int m = lane; m < NM; m += 32) s += p[m];
    #pragma unroll
    for (int off = 16; off; off >>= 1) s += __shfl_xor_sync(0xffffffffu, s, off);
    if (lane == 0) g_w2s[r] = s;
}

__global__ void b2sum_kernel(const float* __restrict__ b2) {
    int e = threadIdx.x >> 5;
    int lane = threadIdx.x & 31;
    float s = 0.f;
    for (int m = lane; m < NM; m += 32) s += b2[e * NM + m];
    #pragma unroll
    for (int off = 16; off; off >>= 1) s += __shfl_xor_sync(0xffffffffu, s, off);
    if (lane == 0) g_b2s[e] = s;
}

// ---------------- router: logits -> softmax -> top-2 -> gates ----------------
// grid: NS blocks x 256 threads
__global__ void router_kernel(const float* __restrict__ x, const float* __restrict__ wg) {
    int s = blockIdx.x;
    int tid = threadIdx.x;
    const float* xr = x + (size_t)s * NM;
    float acc[8];
    #pragma unroll
    for (int e = 0; e < 8; ++e) acc[e] = 0.f;
    for (int m = tid; m < NM; m += 256) {
        float xv = xr[m];
        const float4* w4 = reinterpret_cast<const float4*>(wg + (size_t)m * NE);
        float4 wa = w4[0], wb = w4[1];
        acc[0] += xv * wa.x; acc[1] += xv * wa.y; acc[2] += xv * wa.z; acc[3] += xv * wa.w;
        acc[4] += xv * wb.x; acc[5] += xv * wb.y; acc[6] += xv * wb.z; acc[7] += xv * wb.w;
    }
    #pragma unroll
    for (int off = 16; off; off >>= 1) {
        #pragma unroll
        for (int e = 0; e < 8; ++e) acc[e] += __shfl_xor_sync(0xffffffffu, acc[e], off);
    }
    __shared__ float wsum[8][8];
    int lane = tid & 31, w = tid >> 5;
    if (lane == 0) {
        #pragma unroll
        for (int e = 0; e < 8; ++e) wsum[w][e] = acc[e];
    }
    __syncthreads();
    if (tid == 0) {
        float l[8];
        #pragma unroll
        for (int e = 0; e < 8; ++e) {
            float t = 0.f;
            #pragma unroll
            for (int ww = 0; ww < 8; ++ww) t += wsum[ww][e];
            l[e] = t;
        }
        float mx = l[0];
        #pragma unroll
        for (int e = 1; e < 8; ++e) mx = fmaxf(mx, l[e]);
        float p[8], Z = 0.f;
        #pragma unroll
        for (int e = 0; e < 8; ++e) { p[e] = expf(l[e] - mx); Z += p[e]; }
        // top-2 (ties -> lower index, matching lax.top_k)
        int i0 = 0;
        #pragma unroll
        for (int e = 1; e < 8; ++e) if (l[e] > l[i0]) i0 = e;
        int i1 = (i0 == 0) ? 1 : 0;
        #pragma unroll
        for (int e = 0; e < 8; ++e) if (e != i0 && l[e] > l[i1]) i1 = e;
        float s0 = p[i0] / Z, s1 = p[i1] / Z;
        float denom = s0 + s1 + 1e-9f;
        g_topi[s * 2 + 0] = i0;
        g_topi[s * 2 + 1] = i1;
        g_gate[s * 2 + 0] = s0 / denom;
        g_gate[s * 2 + 1] = s1 / denom;
        g_osum[s] = 0.f;
    }
}

// ---------------- build: ordered rank scan, keep test, compacted lists ----------------
// grid: NE blocks x 1024 threads. Reproduces reference cumsum/offset semantics.
__global__ void build_kernel() {
    int e = blockIdx.x;
    int tid = threadIdx.x;
    int lane = tid & 31, wrp = tid >> 5;
    __shared__ int wsum[32];
    int base = 0;  // running count of assignments to e (incl. dropped), across slots
    float b2s = g_b2s[e];
    for (int j = 0; j < 2; ++j) {
        for (int chunk = 0; chunk < NS; chunk += 1024) {
            int s = chunk + tid;
            int f = (g_topi[s * 2 + j] == e) ? 1 : 0;
            unsigned bal = __ballot_sync(0xffffffffu, f);
            int incl_w = __popc(bal & ((2u << lane) - 1u));  // inclusive within warp
            if (lane == 0) wsum[wrp] = __popc(bal);
            __syncthreads();
            if (wrp == 0) {
                int v = wsum[lane];
                #pragma unroll
                for (int off = 1; off < 32; off <<= 1) {
                    int n = __shfl_up_sync(0xffffffffu, v, off);
                    if (lane >= off) v += n;
                }
                wsum[lane] = v;
            }
            __syncthreads();
            int prev = wrp ? wsum[wrp - 1] : 0;
            int incl = prev + incl_w;
            int total = wsum[31];
            if (f) {
                int pos = base + incl - 1;
                if (pos < NC) {
                    g_tok[e * NC + pos] = s;
                    float g = g_gate[s * 2 + j];
                    g_gts[e * NC + pos] = g;
                    atomicAdd(&g_osum[s], g * b2s);  // fold in b2-sum term once
                }
            }
            base += total;
            __syncthreads();
        }
    }
    int ne = base < NC ? base : NC;
    if (tid == 0) g_ne[e] = ne;
    for (int pos = ne + tid; pos < NC; pos += 1024) {  // pad: gate 0 => no-op rows
        g_tok[e * NC + pos] = 0;
        g_gts[e * NC + pos] = 0.f;
    }
}

// ---------------- grouped expert GEMM, fused relu + w2sum dot + scatter ----------------
// grid: (NC/128, NH/128, NE), 256 threads, 8x8 microtile as f32x2 pairs.
__global__ __launch_bounds__(256, 2)
void expert_gemm_kernel(const float* __restrict__ x, const float* __restrict__ w1,
                        const float* __restrict__ b1) {
    constexpr int BM = 128, BH = 128, BK = 16;
    int e = blockIdx.z;
    int ne = g_ne[e];
    int row0 = blockIdx.x * BM;
    if (row0 >= ne) return;
    int h0 = blockIdx.y * BH;

    __shared__ __align__(16) float As[BK][BM];
    __shared__ __align__(16) float Bs[BK][BH];
    __shared__ float s_rowsum[BM];
    __shared__ int   s_tok[BM];
    __shared__ float s_gate[BM];

    int tid = threadIdx.x;
    if (tid < BM) {
        s_tok[tid] = g_tok[e * NC + row0 + tid];
        s_gate[tid] = g_gts[e * NC + row0 + tid];
        s_rowsum[tid] = 0.f;
    }
    __syncthreads();

    const float* w1e = w1 + (size_t)e * NM * NH;

    // A loader: thread -> (row ar in tile, float4 cols ac, ac+1)
    int ar = tid >> 1;
    int ac = (tid & 1) * 2;
    const float4* aptr = reinterpret_cast<const float4*>(x + (size_t)s_tok[ar] * NM) + ac;
    // B loader: thread -> (k-row brow, float4 cols bc, bc+1)
    int brow = tid >> 4;
    int bc = (tid & 15) * 2;
    const float4* bptr = reinterpret_cast<const float4*>(w1e + (size_t)brow * NH + h0) + bc;
    constexpr int BSTRIDE = BK * NH / 4;  // float4 stride per k-tile for B

    int tx = tid & 15, ty = tid >> 4;

    unsigned long long acc[8][4];
    #pragma unroll
    for (int i = 0; i < 8; ++i)
        #pragma unroll
        for (int jp = 0; jp < 4; ++jp) acc[i][jp] = 0ULL;

    // prefetch tile 0
    float4 arg0 = aptr[0], arg1 = aptr[1];
    float4 brg0 = bptr[0], brg1 = bptr[1];

    constexpr int NTILES = NM / BK;  // 64
    #pragma unroll 1
    for (int t = 0; t < NTILES; ++t) {
        As[ac * 4 + 0][ar] = arg0.x; As[ac * 4 + 1][ar] = arg0.y;
        As[ac * 4 + 2][ar] = arg0.z; As[ac * 4 + 3][ar] = arg0.w;
        As[ac * 4 + 4][ar] = arg1.x; As[ac * 4 + 5][ar] = arg1.y;
        As[ac * 4 + 6][ar] = arg1.z; As[ac * 4 + 7][ar] = arg1.w;
        *reinterpret_cast<float4*>(&Bs[brow][bc * 4]) = brg0;
        *reinterpret_cast<float4*>(&Bs[brow][bc * 4 + 4]) = brg1;
        __syncthreads();
        if (t + 1 < NTILES) {  // register prefetch of next tile (hides GMEM latency)
            arg0 = aptr[(t + 1) * 4];
            arg1 = aptr[(t + 1) * 4 + 1];
            brg0 = bptr[(size_t)(t + 1) * BSTRIDE];
            brg1 = bptr[(size_t)(t + 1) * BSTRIDE + 1];
        }
        #pragma unroll
        for (int kk = 0; kk < BK; ++kk) {
            float4 a0 = *reinterpret_cast<const float4*>(&As[kk][ty * 8]);
            float4 a1 = *reinterpret_cast<const float4*>(&As[kk][ty * 8 + 4]);
            float4 b0 = *reinterpret_cast<const float4*>(&Bs[kk][tx * 8]);
            float4 b1v = *reinterpret_cast<const float4*>(&Bs[kk][tx * 8 + 4]);
            unsigned long long bp0 = pack2(b0.x, b0.y);
            unsigned long long bp1 = pack2(b0.z, b0.w);
            unsigned long long bp2 = pack2(b1v.x, b1v.y);
            unsigned long long bp3 = pack2(b1v.z, b1v.w);
            float ra[8] = {a0.x, a0.y, a0.z, a0.w, a1.x, a1.y, a1.z, a1.w};
            #pragma unroll
            for (int i = 0; i < 8; ++i) {
                unsigned long long av = pack2(ra[i], ra[i]);
                fma2(acc[i][0], av, bp0);
                fma2(acc[i][1], av, bp1);
                fma2(acc[i][2], av, bp2);
                fma2(acc[i][3], av, bp3);
            }
        }
        __syncthreads();
    }

    // fused epilogue: +b1, relu, dot with w2sum, reduce across tx, scatter-add
    int hbase = h0 + tx * 8;
    const float* b1e = b1 + (size_t)e * NH + hbase;
    const float* w2se = g_w2s + (size_t)e * NH + hbase;
    float4 bbv0 = *reinterpret_cast<const float4*>(b1e);
    float4 bbv1 = *reinterpret_cast<const float4*>(b1e + 4);
    float4 wwv0 = *reinterpret_cast<const float4*>(w2se);
    float4 wwv1 = *reinterpret_cast<const float4*>(w2se + 4);
    float bb[8] = {bbv0.x, bbv0.y, bbv0.z, bbv0.w, bbv1.x, bbv1.y, bbv1.z, bbv1.w};
    float ww[8] = {wwv0.x, wwv0.y, wwv0.z, wwv0.w, wwv1.x, wwv1.y, wwv1.z, wwv1.w};
    int lane = tid & 31;
    #pragma unroll
    for (int i = 0; i < 8; ++i) {
        float rs = 0.f;
        #pragma unroll
        for (int jp = 0; jp < 4; ++jp) {
            float2 c = unpack2(acc[i][jp]);
            rs += fmaxf(c.x + bb[jp * 2], 0.f) * ww[jp * 2];
            rs += fmaxf(c.y + bb[jp * 2 + 1], 0.f) * ww[jp * 2 + 1];
        }
        rs += __shfl_xor_sync(0xffffffffu, rs, 1);
        rs += __shfl_xor_sync(0xffffffffu, rs, 2);
        rs += __shfl_xor_sync(0xffffffffu, rs, 4);
        rs += __shfl_xor_sync(0xffffffffu, rs, 8);
        if ((lane & 15) == 0) atomicAdd(&s_rowsum[ty * 8 + i], rs);
    }
    __syncthreads();
    if (tid < BM) {
        int r = row0 + tid;
        if (r < ne) atomicAdd(&g_osum[s_tok[tid]], s_gate[tid] * s_rowsum[tid]);
    }
}

// ---------------- per-batch log_softmax over T ----------------
// grid: NB blocks x 1024 threads (2 elements each)
__global__ void logsoftmax_kernel(float* __restrict__ out) {
    int b = blockIdx.x;
    int tid = threadIdx.x;
    int lane = tid & 31, w = tid >> 5;
    const float* row = g_osum + (size_t)b * NT;
    float v0 = row[tid], v1 = row[tid + 1024];
    __shared__ float sm[32];

    float m = fmaxf(v0, v1);
    #pragma unroll
    for (int off = 16; off; off >>= 1) m = fmaxf(m, __shfl_xor_sync(0xffffffffu, m, off));
    if (lane == 0) sm[w] = m;
    __syncthreads();
    if (w == 0) {
        float t = sm[lane];
        #pragma unroll
        for (int off = 16; off; off >>= 1) t = fmaxf(t, __shfl_xor_sync(0xffffffffu, t, off));
        if (lane == 0) sm[0] = t;
    }
    __syncthreads();
    float MX = sm[0];
    __syncthreads();

    float se = expf(v0 - MX) + expf(v1 - MX);
    #pragma unroll
    for (int off = 16; off; off >>= 1) se += __shfl_xor_sync(0xffffffffu, se, off);
    if (lane == 0) sm[w] = se;
    __syncthreads();
    if (w == 0) {
        float t = sm[lane];
        #pragma unroll
        for (int off = 16; off; off >>= 1) t += __shfl_xor_sync(0xffffffffu, t, off);
        if (lane == 0) sm[0] = logf(t);
    }
    __syncthreads();
    float LS = sm[0];
    out[(size_t)b * NT + tid] = v0 - MX - LS;
    out[(size_t)b * NT + tid + 1024] = v1 - MX - LS;
}

// ---------------- launch ----------------
extern "C" void kernel_launch(void* const* d_in, const int* in_sizes, int n_in,
                              void* d_out, int out_size) {
    const float* x  = (const float*)d_in[0];
    const float* wg = (const float*)d_in[1];
    const float* w1 = (const float*)d_in[2];
    const float* b1 = (const float*)d_in[3];
    const float* w2 = (const float*)d_in[4];
    const float* b2 = (const float*)d_in[5];
    float* out = (float*)d_out;
    (void)in_sizes; (void)n_in; (void)out_size;

    w2sum_kernel<<<NE * NH / 8, 256>>>(w2);
    b2sum_kernel<<<1, 256>>>(b2);
    router_kernel<<<NS, 256>>>(x, wg);
    build_kernel<<<NE, 1024>>>();
    expert_gemm_kernel<<<dim3(NC / 128, NH / 128, NE), 256>>>(x, w1, b1);
    logsoftmax_kernel<<<NB, 1024>>>(out);
}

// round 13
// speedup vs baseline: 2.2065x; 2.2065x over previous
#include <cuda_runtime.h>
#include <cuda_bf16.h>
#include <cstdint>
#include <cstddef>

// ---------------- problem constants ----------------
#define NB 4
#define NT 2048
#define NM 1024
#define NH 2048
#define NE 8
#define NS (NB * NT)       // 8192 tokens
#define NC 2048            // expert capacity

// GEMM tiling
#define BM 128             // tokens per CTA
#define BN 256             // h cols per CTA
#define BKT 32             // K per stage
#define NKT (NM / BKT)     // 32 stages
// smem stage layout (bytes): Ah | Al | Bh | Bl, padded rows of 80B (32 bf16 + 8 pad)
#define ROWB 80
#define OFF_AL 10240       // 128*80
#define OFF_BH 20480
#define OFF_BL 40960       // 20480 + 256*80
#define STAGE  61440
#define SMEM_DYN (2 * STAGE)

// ---------------- device scratch (no allocs allowed) ----------------
__device__ int   g_topi[NS * 2];
__device__ float g_gate[NS * 2];
__device__ int   g_tok[NE * NC];
__device__ float g_gts[NE * NC];
__device__ int   g_ne[NE];
__device__ __align__(16) float g_w2s[NE * NH];
__device__ float g_b2s[NE];
__device__ float g_osum[NS];
__device__ __align__(16) __nv_bfloat16 g_xh[(size_t)NS * NM];
__device__ __align__(16) __nv_bfloat16 g_xl[(size_t)NS * NM];
__device__ __align__(16) __nv_bfloat16 g_w1h[(size_t)NE * NH * NM];  // [e][h][m]
__device__ __align__(16) __nv_bfloat16 g_w1l[(size_t)NE * NH * NM];

// ---------------- helpers ----------------
__device__ __forceinline__ uint32_t smem_u32(const void* p) {
    uint32_t a;
    asm("{ .reg .u64 t; cvta.to.shared.u64 t, %1; cvt.u32.u64 %0, t; }"
        : "=r"(a) : "l"(p));
    return a;
}
__device__ __forceinline__ void cp16(uint32_t dst, const void* src) {
    asm volatile("cp.async.cg.shared.global [%0], [%1], 16;"
                 :: "r"(dst), "l"(src));
}
__device__ __forceinline__ void cp_commit() {
    asm volatile("cp.async.commit_group;" ::: "memory");
}
__device__ __forceinline__ void cp_wait1() {
    asm volatile("cp.async.wait_group 1;" ::: "memory");
}
__device__ __forceinline__ void cp_wait0() {
    asm volatile("cp.async.wait_group 0;" ::: "memory");
}
__device__ __forceinline__ uint32_t ld32s(const char* p) {
    return *reinterpret_cast<const uint32_t*>(p);
}
// m16n8k16 row.col f32 <- bf16 x bf16 + f32 (sm_80 PTX; fallback HMMA on sm_103)
__device__ __forceinline__ void mma_bf16(float* d, const uint32_t* a, const uint32_t* b) {
    asm volatile(
        "mma.sync.aligned.m16n8k16.row.col.f32.bf16.bf16.f32 "
        "{%0,%1,%2,%3}, {%4,%5,%6,%7}, {%8,%9}, {%0,%1,%2,%3};\n"
        : "+f"(d[0]), "+f"(d[1]), "+f"(d[2]), "+f"(d[3])
        : "r"(a[0]), "r"(a[1]), "r"(a[2]), "r"(a[3]), "r"(b[0]), "r"(b[1]));
}

// ---------------- x split: fp32 -> bf16 hi/lo planes ----------------
__global__ void split_x(const float* __restrict__ x) {
    size_t i4 = (size_t)(blockIdx.x * 256 + threadIdx.x) * 4;
    float4 v = *reinterpret_cast<const float4*>(x + i4);
    float vv[4] = {v.x, v.y, v.z, v.w};
    #pragma unroll
    for (int j = 0; j < 4; ++j) {
        __nv_bfloat16 h = __float2bfloat16_rn(vv[j]);
        g_xh[i4 + j] = h;
        g_xl[i4 + j] = __float2bfloat16_rn(vv[j] - __bfloat162float(h));
    }
}

// ---------------- w1 transpose + split: [e][m][h] -> hi/lo [e][h][m] ----------------
__global__ void transpose_split_w1(const float* __restrict__ w1) {
    __shared__ float tile[32][33];
    int e = blockIdx.z;
    int m0 = blockIdx.x * 32, h0 = blockIdx.y * 32;
    const float* src = w1 + (size_t)e * NM * NH;
    int tx = threadIdx.x, ty = threadIdx.y;
    #pragma unroll
    for (int i = 0; i < 32; i += 8)
        tile[ty + i][tx] = src[(size_t)(m0 + ty + i) * NH + h0 + tx];
    __syncthreads();
    size_t dbase = (size_t)e * NH * NM;
    #pragma unroll
    for (int i = 0; i < 32; i += 8) {
        float v = tile[tx][ty + i];
        __nv_bfloat16 h = __float2bfloat16_rn(v);
        size_t di = dbase + (size_t)(h0 + ty + i) * NM + m0 + tx;
        g_w1h[di] = h;
        g_w1l[di] = __float2bfloat16_rn(v - __bfloat162float(h));
    }
}

// ---------------- w2 column-sum ----------------
__global__ void w2sum_kernel(const float* __restrict__ w2) {
    int r = blockIdx.x * 8 + (threadIdx.x >> 5);
    int lane = threadIdx.x & 31;
    const float* p = w2 + (size_t)r * NM;
    float s = 0.f;
    #pragma unroll 4
    for (int m = lane; m < NM; m += 32) s += p[m];
    #pragma unroll
    for (int off = 16; off; off >>= 1) s += __shfl_xor_sync(0xffffffffu, s, off);
    if (lane == 0) g_w2s[r] = s;
}

__global__ void b2sum_kernel(const float* __restrict__ b2) {
    int e = threadIdx.x >> 5;
    int lane = threadIdx.x & 31;
    float s = 0.f;
    for (int m = lane; m < NM; m += 32) s += b2[e * NM + m];
    #pragma unroll
    for (int off = 16; off; off >>= 1) s += __shfl_xor_sync(0xffffffffu, s, off);
    if (lane == 0) g_b2s[e] = s;
}

// ---------------- router ----------------
__global__ void router_kernel(const float* __restrict__ x, const float* __restrict__ wg) {
    int s = blockIdx.x;
    int tid = threadIdx.x;
    const float* xr = x + (size_t)s * NM;
    float acc[8];
    #pragma unroll
    for (int e = 0; e < 8; ++e) acc[e] = 0.f;
    for (int m = tid; m < NM; m += 256) {
        float xv = xr[m];
        const float4* w4 = reinterpret_cast<const float4*>(wg + (size_t)m * NE);
        float4 wa = w4[0], wb = w4[1];
        acc[0] += xv * wa.x; acc[1] += xv * wa.y; acc[2] += xv * wa.z; acc[3] += xv * wa.w;
        acc[4] += xv * wb.x; acc[5] += xv * wb.y; acc[6] += xv * wb.z; acc[7] += xv * wb.w;
    }
    #pragma unroll
    for (int off = 16; off; off >>= 1) {
        #pragma unroll
        for (int e = 0; e < 8; ++e) acc[e] += __shfl_xor_sync(0xffffffffu, acc[e], off);
    }
    __shared__ float wsum[8][8];
    int lane = tid & 31, w = tid >> 5;
    if (lane == 0) {
        #pragma unroll
        for (int e = 0; e < 8; ++e) wsum[w][e] = acc[e];
    }
    __syncthreads();
    if (tid == 0) {
        float l[8];
        #pragma unroll
        for (int e = 0; e < 8; ++e) {
            float t = 0.f;
            #pragma unroll
            for (int ww = 0; ww < 8; ++ww) t += wsum[ww][e];
            l[e] = t;
        }
        float mx = l[0];
        #pragma unroll
        for (int e = 1; e < 8; ++e) mx = fmaxf(mx, l[e]);
        float p[8], Z = 0.f;
        #pragma unroll
        for (int e = 0; e < 8; ++e) { p[e] = expf(l[e] - mx); Z += p[e]; }
        int i0 = 0;
        #pragma unroll
        for (int e = 1; e < 8; ++e) if (l[e] > l[i0]) i0 = e;
        int i1 = (i0 == 0) ? 1 : 0;
        #pragma unroll
        for (int e = 0; e < 8; ++e) if (e != i0 && l[e] > l[i1]) i1 = e;
        float s0 = p[i0] / Z, s1 = p[i1] / Z;
        float denom = s0 + s1 + 1e-9f;
        g_topi[s * 2 + 0] = i0;
        g_topi[s * 2 + 1] = i1;
        g_gate[s * 2 + 0] = s0 / denom;
        g_gate[s * 2 + 1] = s1 / denom;
        g_osum[s] = 0.f;
    }
}

// ---------------- build: ordered rank scan ----------------
__global__ void build_kernel() {
    int e = blockIdx.x;
    int tid = threadIdx.x;
    int lane = tid & 31, wrp = tid >> 5;
    __shared__ int wsum[32];
    int base = 0;
    float b2s = g_b2s[e];
    for (int j = 0; j < 2; ++j) {
        for (int chunk = 0; chunk < NS; chunk += 1024) {
            int s = chunk + tid;
            int f = (g_topi[s * 2 + j] == e) ? 1 : 0;
            unsigned bal = __ballot_sync(0xffffffffu, f);
            int incl_w = __popc(bal & ((2u << lane) - 1u));
            if (lane == 0) wsum[wrp] = __popc(bal);
            __syncthreads();
            if (wrp == 0) {
                int v = wsum[lane];
                #pragma unroll
                for (int off = 1; off < 32; off <<= 1) {
                    int n = __shfl_up_sync(0xffffffffu, v, off);
                    if (lane >= off) v += n;
                }
                wsum[lane] = v;
            }
            __syncthreads();
            int prev = wrp ? wsum[wrp - 1] : 0;
            int incl = prev + incl_w;
            int total = wsum[31];
            if (f) {
                int pos = base + incl - 1;
                if (pos < NC) {
                    g_tok[e * NC + pos] = s;
                    float g = g_gate[s * 2 + j];
                    g_gts[e * NC + pos] = g;
                    atomicAdd(&g_osum[s], g * b2s);
                }
            }
            base += total;
            __syncthreads();
        }
    }
    int ne = base < NC ? base : NC;
    if (tid == 0) g_ne[e] = ne;
    for (int pos = ne + tid; pos < NC; pos += 1024) {
        g_tok[e * NC + pos] = 0;
        g_gts[e * NC + pos] = 0.f;
    }
}

// ---------------- grouped GEMM: mma.sync bf16 3-product, fused epilogue ----------------
// grid (NC/BM=16, NH/BN=8, NE=8), 256 threads, 2-stage cp.async pipeline.
__global__ __launch_bounds__(256, 1)
void expert_gemm_mma(const float* __restrict__ b1) {
    int e = blockIdx.z;
    int ne = g_ne[e];
    int row0 = blockIdx.x * BM;
    if (row0 >= ne) return;
    int h0 = blockIdx.y * BN;

    extern __shared__ __align__(16) char dsm[];
    __shared__ int   s_tok[BM];
    __shared__ float s_gate[BM];
    __shared__ float s_bb[BN], s_ww[BN];
    __shared__ float s_rs[BM];

    int tid = threadIdx.x;
    int lane = tid & 31, warp = tid >> 5;
    int gid = lane >> 2, tig = lane & 3;
    int wm = warp >> 2, wn = warp & 3;   // warp tile: 64x64 at (wm*64, wn*64)

    if (tid < BM) {
        s_tok[tid]  = g_tok[e * NC + row0 + tid];
        s_gate[tid] = g_gts[e * NC + row0 + tid];
        s_rs[tid] = 0.f;
    }
    // 256 threads cover all BN=256 entries exactly once (R7 bug: the extra
    // tid+128 duplicate stores overflowed s_bb/s_ww into s_ww/s_rs).
    s_bb[tid] = b1[(size_t)e * NH + h0 + tid];
    s_ww[tid] = g_w2s[(size_t)e * NH + h0 + tid];
    __syncthreads();

    // loader plan: 16B chunks. A planes: 128 rows x 4 chunks -> 2/thread.
    // B planes: 256 rows x 4 chunks -> 4/thread.
    size_t offA[2];  uint32_t dA[2];
    size_t offB[4];  uint32_t dB[4];
    #pragma unroll
    for (int i = 0; i < 2; ++i) {
        int u = tid + 256 * i;
        int row = u >> 2, c = u & 3;
        offA[i] = (size_t)s_tok[row] * NM + c * 8;
        dA[i] = row * ROWB + c * 16;
    }
    #pragma unroll
    for (int i = 0; i < 4; ++i) {
        int u = tid + 256 * i;
        int row = u >> 2, c = u & 3;
        offB[i] = ((size_t)e * NH + h0 + row) * NM + c * 8;
        dB[i] = row * ROWB + c * 16;
    }
    uint32_t smemU = smem_u32(dsm);

    float acc[4][8][4];
    #pragma unroll
    for (int im = 0; im < 4; ++im)
        #pragma unroll
        for (int in = 0; in < 8; ++in)
            #pragma unroll
            for (int q = 0; q < 4; ++q) acc[im][in][q] = 0.f;

    // prologue: stage 0
    {
        uint32_t sb = smemU;
        #pragma unroll
        for (int i = 0; i < 2; ++i) {
            cp16(sb + dA[i], g_xh + offA[i]);
            cp16(sb + OFF_AL + dA[i], g_xl + offA[i]);
        }
        #pragma unroll
        for (int i = 0; i < 4; ++i) {
            cp16(sb + OFF_BH + dB[i], g_w1h + offB[i]);
            cp16(sb + OFF_BL + dB[i], g_w1l + offB[i]);
        }
        cp_commit();
    }

    #pragma unroll 1
    for (int kt = 0; kt < NKT; ++kt) {
        if (kt + 1 < NKT) {
            uint32_t sb = smemU + ((kt + 1) & 1) * STAGE;
            int ko = (kt + 1) * BKT;
            #pragma unroll
            for (int i = 0; i < 2; ++i) {
                cp16(sb + dA[i], g_xh + offA[i] + ko);
                cp16(sb + OFF_AL + dA[i], g_xl + offA[i] + ko);
            }
            #pragma unroll
            for (int i = 0; i < 4; ++i) {
                cp16(sb + OFF_BH + dB[i], g_w1h + offB[i] + ko);
                cp16(sb + OFF_BL + dB[i], g_w1l + offB[i] + ko);
            }
            cp_commit();
            cp_wait1();
        } else {
            cp_wait0();
        }
        __syncthreads();

        const char* bp = dsm + (kt & 1) * STAGE;
        const char* AH = bp;
        const char* AL = bp + OFF_AL;
        const char* BH = bp + OFF_BH;
        const char* BL = bp + OFF_BL;

        #pragma unroll
        for (int ks = 0; ks < 2; ++ks) {
            int kByte = (ks * 16 + 2 * tig) * 2;
            uint32_t bh[8][2], bl[8][2];
            #pragma unroll
            for (int in = 0; in < 8; ++in) {
                const char* pbh = BH + (wn * 64 + in * 8 + gid) * ROWB + kByte;
                const char* pbl = BL + (wn * 64 + in * 8 + gid) * ROWB + kByte;
                bh[in][0] = ld32s(pbh); bh[in][1] = ld32s(pbh + 16);
                bl[in][0] = ld32s(pbl); bl[in][1] = ld32s(pbl + 16);
            }
            #pragma unroll
            for (int im = 0; im < 4; ++im) {
                const char* pah = AH + (wm * 64 + im * 16 + gid) * ROWB + kByte;
                const char* pal = AL + (wm * 64 + im * 16 + gid) * ROWB + kByte;
                uint32_t ah[4] = {ld32s(pah), ld32s(pah + 8 * ROWB),
                                  ld32s(pah + 16), ld32s(pah + 8 * ROWB + 16)};
                uint32_t al[4] = {ld32s(pal), ld32s(pal + 8 * ROWB),
                                  ld32s(pal + 16), ld32s(pal + 8 * ROWB + 16)};
                #pragma unroll
                for (int in = 0; in < 8; ++in) {
                    mma_bf16(acc[im][in], ah, bh[in]);   // hi*hi
                    mma_bf16(acc[im][in], ah, bl[in]);   // hi*lo
                    mma_bf16(acc[im][in], al, bh[in]);   // lo*hi
                }
            }
        }
        __syncthreads();
    }

    // fused epilogue: relu(D + b1) . w2sum -> rowsum -> gate scatter
    #pragma unroll
    for (int im = 0; im < 4; ++im) {
        float rs0 = 0.f, rs1 = 0.f;
        #pragma unroll
        for (int in = 0; in < 8; ++in) {
            int col = wn * 64 + in * 8 + 2 * tig;
            float w0 = s_ww[col], w1v = s_ww[col + 1];
            float bb0 = s_bb[col], bb1 = s_bb[col + 1];
            rs0 += fmaxf(acc[im][in][0] + bb0, 0.f) * w0
                 + fmaxf(acc[im][in][1] + bb1, 0.f) * w1v;
            rs1 += fmaxf(acc[im][in][2] + bb0, 0.f) * w0
                 + fmaxf(acc[im][in][3] + bb1, 0.f) * w1v;
        }
        rs0 += __shfl_xor_sync(0xffffffffu, rs0, 1);
        rs0 += __shfl_xor_sync(0xffffffffu, rs0, 2);
        rs1 += __shfl_xor_sync(0xffffffffu, rs1, 1);
        rs1 += __shfl_xor_sync(0xffffffffu, rs1, 2);
        if (tig == 0) {
            int r = wm * 64 + im * 16 + gid;
            atomicAdd(&s_rs[r], rs0);
            atomicAdd(&s_rs[r + 8], rs1);
        }
    }
    __syncthreads();
    if (tid < BM) {
        int r = row0 + tid;
        if (r < ne)
            atomicAdd(&g_osum[s_tok[tid]], s_gate[tid] * s_rs[tid]);
    }
}

// ---------------- per-batch log_softmax over T ----------------
__global__ void logsoftmax_kernel(float* __restrict__ out) {
    int b = blockIdx.x;
    int tid = threadIdx.x;
    int lane = tid & 31, w = tid >> 5;
    const float* row = g_osum + (size_t)b * NT;
    float v0 = row[tid], v1 = row[tid + 1024];
    __shared__ float sm[32];

    float m = fmaxf(v0, v1);
    #pragma unroll
    for (int off = 16; off; off >>= 1) m = fmaxf(m, __shfl_xor_sync(0xffffffffu, m, off));
    if (lane == 0) sm[w] = m;
    __syncthreads();
    if (w == 0) {
        float t = sm[lane];
        #pragma unroll
        for (int off = 16; off; off >>= 1) t = fmaxf(t, __shfl_xor_sync(0xffffffffu, t, off));
        if (lane == 0) sm[0] = t;
    }
    __syncthreads();
    float MX = sm[0];
    __syncthreads();

    float se = expf(v0 - MX) + expf(v1 - MX);
    #pragma unroll
    for (int off = 16; off; off >>= 1) se += __shfl_xor_sync(0xffffffffu, se, off);
    if (lane == 0) sm[w] = se;
    __syncthreads();
    if (w == 0) {
        float t = sm[lane];
        #pragma unroll
        for (int off = 16; off; off >>= 1) t += __shfl_xor_sync(0xffffffffu, t, off);
        if (lane == 0) sm[0] = logf(t);
    }
    __syncthreads();
    float LS = sm[0];
    out[(size_t)b * NT + tid] = v0 - MX - LS;
    out[(size_t)b * NT + tid + 1024] = v1 - MX - LS;
}

// ---------------- launch ----------------
extern "C" void kernel_launch(void* const* d_in, const int* in_sizes, int n_in,
                              void* d_out, int out_size) {
    const float* x  = (const float*)d_in[0];
    const float* wg = (const float*)d_in[1];
    const float* w1 = (const float*)d_in[2];
    const float* b1 = (const float*)d_in[3];
    const float* w2 = (const float*)d_in[4];
    const float* b2 = (const float*)d_in[5];
    float* out = (float*)d_out;
    (void)in_sizes; (void)n_in; (void)out_size;

    cudaFuncSetAttribute(expert_gemm_mma,
                         cudaFuncAttributeMaxDynamicSharedMemorySize, SMEM_DYN);

    split_x<<<NS * NM / 1024, 256>>>(x);
    transpose_split_w1<<<dim3(NM / 32, NH / 32, NE), dim3(32, 8)>>>(w1);
    w2sum_kernel<<<NE * NH / 8, 256>>>(w2);
    b2sum_kernel<<<1, 256>>>(b2);
    router_kernel<<<NS, 256>>>(x, wg);
    build_kernel<<<NE, 1024>>>();
    expert_gemm_mma<<<dim3(NC / BM, NH / BN, NE), 256, SMEM_DYN>>>(b1);
    logsoftmax_kernel<<<NB, 1024>>>(out);
}